// round 12
// baseline (speedup 1.0000x reference)
#include <cuda_runtime.h>
#include <math.h>

#define NMAX 100000
#define EMAX 1600000
#define ETMAX (NMAX + EMAX)

// -------- scratch (device globals) -----------------------------------------
// RULE (root cause of rounds 2-9): these symbols must NEVER appear in a
// kernel<<<>>> argument list from host code — host sees only the shadow
// address, and GB300's ATS makes writes through it silently land in host
// memory. All access is via device-side symbol references / scratch(sel).
__device__ __align__(16) float g_xl[(size_t)NMAX * 128];
__device__ __align__(16) float g_xr[(size_t)NMAX * 128];
__device__ __align__(16) float g_h [(size_t)NMAX * 128];
__device__ int g_deg [NMAX + 2];
__device__ int g_off [NMAX + 2];
__device__ int g_bsum[1024];
__device__ int g_srcs[ETMAX];

__device__ __forceinline__ float* scratch(int b) {
    return (b == 0) ? g_xl : (b == 1) ? g_xr : g_h;
}

static inline int ceil_div(int a, int b) { return (a + b - 1) / b; }

// ============================ CSR build ====================================
__global__ void k_zero_deg(int n) {
    int i = blockIdx.x * blockDim.x + threadIdx.x;
    if (i < n) g_deg[i] = 0;
}

__global__ void k_count(const int* __restrict__ ei, int E, int n) {
    int e = blockIdx.x * blockDim.x + threadIdx.x;
    if (e >= E + n) return;
    int dst = (e < E) ? ei[E + e] : (e - E);   // self-loops appended after edges
    atomicAdd(&g_deg[dst], 1);
}

__global__ void k_scan1(int n) {
    __shared__ int sm[1024];
    int tid = threadIdx.x;
    int i = blockIdx.x * 1024 + tid;
    int v = (i < n) ? g_deg[i] : 0;
    sm[tid] = v;
    __syncthreads();
    for (int s = 1; s < 1024; s <<= 1) {
        int t = (tid >= s) ? sm[tid - s] : 0;
        __syncthreads();
        sm[tid] += t;
        __syncthreads();
    }
    if (i < n) g_off[i] = sm[tid] - v;         // exclusive
    if (tid == 1023) g_bsum[blockIdx.x] = sm[1023];
}

__global__ void k_scan2(int nb) {
    __shared__ int sm[1024];
    int tid = threadIdx.x;
    int v = (tid < nb) ? g_bsum[tid] : 0;
    sm[tid] = v;
    __syncthreads();
    for (int s = 1; s < 1024; s <<= 1) {
        int t = (tid >= s) ? sm[tid - s] : 0;
        __syncthreads();
        sm[tid] += t;
        __syncthreads();
    }
    if (tid < nb) g_bsum[tid] = sm[tid] - v;   // exclusive block prefix
}

// add block prefixes, publish sentinel, init cursor (deg <- off)
__global__ void k_scan3(int n, int total) {
    int i = blockIdx.x * blockDim.x + threadIdx.x;
    if (i < n) {
        int o = g_off[i] + g_bsum[i >> 10];
        g_off[i] = o;
        g_deg[i] = o;
    }
    if (i == 0) g_off[n] = total;
}

__global__ void k_fill(const int* __restrict__ ei, int E, int n) {
    int e = blockIdx.x * blockDim.x + threadIdx.x;
    if (e >= E + n) return;
    int s, d;
    if (e < E) { s = ei[e]; d = ei[E + e]; }
    else       { s = e - E; d = s; }
    int pos = atomicAdd(&g_deg[d], 1);
    g_srcs[pos] = s;
}

// ============================ dense linear =================================
// Y[n,O] = X[n,I] @ W[I,O] + B[O]. X via xsel (-1 = external), Y via ysel.
__global__ void k_linear(const float* __restrict__ Xext,
                         const float* __restrict__ W,
                         const float* __restrict__ B,
                         int xsel, int ysel, int n, int I, int O) {
    const float* X = (xsel < 0) ? Xext : scratch(xsel);
    float* Y = scratch(ysel);

    extern __shared__ float sW[];
    for (int i = threadIdx.x; i < I * O; i += blockDim.x) sW[i] = W[i];
    __syncthreads();

    int nc4 = O >> 2;
    int c4  = threadIdx.x & (nc4 - 1);
    int rl  = threadIdx.x / nc4;
    int rpb = (blockDim.x / nc4) * 4;
    int r0  = blockIdx.x * rpb + rl * 4;

    float4 bias4 = *(const float4*)(B + 4 * c4);
    float4 acc[4];
#pragma unroll
    for (int r = 0; r < 4; r++) acc[r] = bias4;

    float xreg[4][4];
    for (int k = 0; k < I; k += 4) {
#pragma unroll
        for (int r = 0; r < 4; r++) {
            float4 t = make_float4(0.f, 0.f, 0.f, 0.f);
            if (r0 + r < n) t = *(const float4*)(X + (size_t)(r0 + r) * I + k);
            xreg[r][0] = t.x; xreg[r][1] = t.y; xreg[r][2] = t.z; xreg[r][3] = t.w;
        }
#pragma unroll
        for (int kk = 0; kk < 4; kk++) {
            float4 w = *(const float4*)(sW + (size_t)(k + kk) * O + 4 * c4);
#pragma unroll
            for (int r = 0; r < 4; r++) {
                acc[r].x = fmaf(xreg[r][kk], w.x, acc[r].x);
                acc[r].y = fmaf(xreg[r][kk], w.y, acc[r].y);
                acc[r].z = fmaf(xreg[r][kk], w.z, acc[r].z);
                acc[r].w = fmaf(xreg[r][kk], w.w, acc[r].w);
            }
        }
    }
#pragma unroll
    for (int r = 0; r < 4; r++)
        if (r0 + r < n)
            *(float4*)(Y + (size_t)(r0 + r) * O + 4 * c4) = acc[r];
}

// ===================== GATv2 aggregation (gather) ==========================
// One warp per destination node; online softmax over incoming edges.
// C = 32 -> floats per lane V == H; head of element = lane / (32/H).
// Reads g_xl/g_xr/g_off/g_srcs directly; writes g_h. att/bias are d_in ptrs.
template <int H>
__global__ void gat_aggregate(const float* __restrict__ attw,   // [H*32]
                              const float* __restrict__ bias,   // [H*32]
                              int n) {
    constexpr int V  = H;
    constexpr int HC = 32 * H;
    constexpr int G  = 32 / H;

    int warp = (blockIdx.x * blockDim.x + threadIdx.x) >> 5;
    int lane = threadIdx.x & 31;
    if (warp >= n) return;
    const int node = warp;

    float xi[V], aw[V], acc[V];
#pragma unroll
    for (int j = 0; j < V; j++) {
        xi[j]  = g_xr[(size_t)node * HC + lane * V + j];
        aw[j]  = attw[lane * V + j];
        acc[j] = 0.f;
    }
    float m = -1e30f;   // running max (per head, replicated across its group)
    float d = 0.f;      // running sum of exp

    int s0 = g_off[node], s1 = g_off[node + 1];
    for (int base = s0; base < s1; base += 32) {
        int idx   = base + lane;
        int mysrc = (idx < s1) ? g_srcs[idx] : 0;
        int cnt   = min(32, s1 - base);
        for (int i = 0; i < cnt; i++) {
            int s = __shfl_sync(0xffffffffu, mysrc, i);
            float xj[V];
            if constexpr (V == 4) {
                float4 t = *reinterpret_cast<const float4*>(g_xl + (size_t)s * HC + lane * 4);
                xj[0] = t.x; xj[1] = t.y; xj[2] = t.z; xj[3] = t.w;
            } else if constexpr (V == 2) {
                float2 t = *reinterpret_cast<const float2*>(g_xl + (size_t)s * HC + lane * 2);
                xj[0] = t.x; xj[1] = t.y;
            } else {
                xj[0] = g_xl[(size_t)s * HC + lane];
            }
            float p = 0.f;
#pragma unroll
            for (int j = 0; j < V; j++) {
                float e = xi[j] + xj[j];
                e = (e > 0.f) ? e : 0.2f * e;      // leaky_relu slope 0.2
                p = fmaf(e, aw[j], p);
            }
#pragma unroll
            for (int sh = G / 2; sh >= 1; sh >>= 1)
                p += __shfl_xor_sync(0xffffffffu, p, sh);
            float mnew  = fmaxf(m, p);
            float scale = __expf(m - mnew);
            float w     = __expf(p - mnew);
            d = fmaf(d, scale, w);
#pragma unroll
            for (int j = 0; j < V; j++)
                acc[j] = fmaf(acc[j], scale, w * xj[j]);
            m = mnew;
        }
    }
    float inv = 1.f / (d + 1e-16f);
#pragma unroll
    for (int j = 0; j < V; j++) {
        float v = fmaf(acc[j], inv, bias[lane * V + j]);
        g_h[(size_t)node * HC + lane * V + j] = fmaxf(v, 0.f);  // relu
    }
}

// ============================ MLP head =====================================
__global__ void k_mlp(const float* __restrict__ wm1, const float* __restrict__ bm1,
                      const float* __restrict__ wm2, const float* __restrict__ bm2,
                      float* __restrict__ out, int n) {
    __shared__ float s1[32 * 16], sb1[16], s2[16 * 2], sb2[2];
    for (int i = threadIdx.x; i < 512; i += blockDim.x) s1[i] = wm1[i];
    if (threadIdx.x < 16) sb1[threadIdx.x] = bm1[threadIdx.x];
    if (threadIdx.x < 32) s2[threadIdx.x]  = wm2[threadIdx.x];
    if (threadIdx.x < 2)  sb2[threadIdx.x] = bm2[threadIdx.x];
    __syncthreads();

    int i = blockIdx.x * blockDim.x + threadIdx.x;
    if (i >= n) return;

    float hv[32];
#pragma unroll
    for (int k = 0; k < 32; k += 4) {
        float4 t = *(const float4*)(g_h + (size_t)i * 32 + k);
        hv[k] = t.x; hv[k + 1] = t.y; hv[k + 2] = t.z; hv[k + 3] = t.w;
    }
    float hid[16];
#pragma unroll
    for (int j = 0; j < 16; j++) {
        float s = sb1[j];
#pragma unroll
        for (int k = 0; k < 32; k++) s = fmaf(hv[k], s1[k * 16 + j], s);
        hid[j] = fmaxf(s, 0.f);
    }
    float r0 = sb2[0], r1 = sb2[1];
#pragma unroll
    for (int k = 0; k < 16; k++) {
        r0 = fmaf(hid[k], s2[k * 2],     r0);
        r1 = fmaf(hid[k], s2[k * 2 + 1], r1);
    }
    float vm = 1.f / (1.f + expf(-r0)) + 0.5f;   // sigmoid + 0.5
    float va = tanhf(r1) * 180.f;
    out[(size_t)i * 2]     = vm;
    out[(size_t)i * 2 + 1] = va;
}

// ============================ launch =======================================
extern "C" void kernel_launch(void* const* d_in, const int* in_sizes, int n_in,
                              void* d_out, int out_size) {
    const float* x   = (const float*)d_in[0];
    const int*   ei  = (const int*)  d_in[1];
    const float* w1l = (const float*)d_in[2];
    const float* b1l = (const float*)d_in[3];
    const float* w1r = (const float*)d_in[4];
    const float* b1r = (const float*)d_in[5];
    const float* a1  = (const float*)d_in[6];
    const float* c1  = (const float*)d_in[7];
    const float* w2l = (const float*)d_in[8];
    const float* b2l = (const float*)d_in[9];
    const float* w2r = (const float*)d_in[10];
    const float* b2r = (const float*)d_in[11];
    const float* a2  = (const float*)d_in[12];
    const float* c2  = (const float*)d_in[13];
    const float* w3l = (const float*)d_in[14];
    const float* b3l = (const float*)d_in[15];
    const float* w3r = (const float*)d_in[16];
    const float* b3r = (const float*)d_in[17];
    const float* a3  = (const float*)d_in[18];
    const float* c3  = (const float*)d_in[19];
    const float* wm1 = (const float*)d_in[20];
    const float* bm1 = (const float*)d_in[21];
    const float* wm2 = (const float*)d_in[22];
    const float* bm2 = (const float*)d_in[23];
    float* out = (float*)d_out;

    int N  = in_sizes[0] / 64;
    int E  = in_sizes[1] / 2;
    int ET = N + E;

    // ---- CSR by dst ----
    k_zero_deg<<<ceil_div(N, 256), 256>>>(N);
    k_count   <<<ceil_div(ET, 256), 256>>>(ei, E, N);
    int nb = ceil_div(N, 1024);
    k_scan1<<<nb, 1024>>>(N);
    k_scan2<<<1, 1024>>>(nb);
    k_scan3<<<ceil_div(N, 256), 256>>>(N, ET);
    k_fill <<<ceil_div(ET, 256), 256>>>(ei, E, N);

    int agrid = ceil_div(N * 32, 256);

    // ---- layer 1: 64 -> (H=4, C=32) concat=128, relu ----
    k_linear<<<ceil_div(N, 32), 256, 64 * 128 * 4>>>(x, w1l, b1l, -1, 0, N, 64, 128);
    k_linear<<<ceil_div(N, 32), 256, 64 * 128 * 4>>>(x, w1r, b1r, -1, 1, N, 64, 128);
    gat_aggregate<4><<<agrid, 256>>>(a1, c1, N);

    // ---- layer 2: 128 -> (H=2, C=32) concat=64, relu ----
    k_linear<<<ceil_div(N, 64), 256, 128 * 64 * 4>>>(nullptr, w2l, b2l, 2, 0, N, 128, 64);
    k_linear<<<ceil_div(N, 64), 256, 128 * 64 * 4>>>(nullptr, w2r, b2r, 2, 1, N, 128, 64);
    gat_aggregate<2><<<agrid, 256>>>(a2, c2, N);

    // ---- layer 3: 64 -> (H=1, C=32) mean over 1 head == identity, relu ----
    k_linear<<<ceil_div(N, 128), 256, 64 * 32 * 4>>>(nullptr, w3l, b3l, 2, 0, N, 64, 32);
    k_linear<<<ceil_div(N, 128), 256, 64 * 32 * 4>>>(nullptr, w3r, b3r, 2, 1, N, 64, 32);
    gat_aggregate<1><<<agrid, 256>>>(a3, c3, N);

    // ---- MLP head + output transforms ----
    k_mlp<<<ceil_div(N, 256), 256>>>(wm1, bm1, wm2, bm2, out, N);
}